// round 2
// baseline (speedup 1.0000x reference)
#include <cuda_runtime.h>
#include <cstddef>

// Shapes: B=256, L=64, D=1024
// left'[b,k,d] = sum_l Wl[k,l]*left[b,l,d] + bl[k]            (same for right)
// corr[b,i,d]  = sum_j left'[b,j,d]*right'[b, j+63-i, d]      (i in [0,128), row 127 = 0)
// y[b,k,d]     = sum_c sum_t Wconv[k,c,t]*corr[b,c,d+t-1]     (zero-padded in d)

namespace {
constexpr int Lc = 64;
constexpr int Dc = 1024;
constexpr int TILE_D = 64;
constexpr int NS = 66;          // tile cols incl. 1-col halo each side
constexpr int SA = 66;          // stride for A / Bpad tiles
constexpr int SC = 68;          // stride for corr (16B-aligned rows for LDS.128)
constexpr int OFF_WL = 0;                         // 64*64 floats
constexpr int OFF_WR = 4096;                      // 64*64
constexpr int OFF_A  = 8192;                      // 64*66   (left raw -> left')
constexpr int OFF_B  = OFF_A + 64 * SA;           // 192*66  (zero-padded right raw -> right')
constexpr int OFF_C  = OFF_B + 192 * SA;          // 128*68  (corr)
constexpr int SMEM_FLOATS = OFF_C + 128 * SC;     // 33792 floats = 135168 B
constexpr int SMEM_BYTES  = SMEM_FLOATS * 4;
constexpr int WCS = 193;        // Wconv per-k stride (aliased at OFF_B; 64*193 <= 192*66)
}

__global__ void __launch_bounds__(256, 1)
cc_fused_kernel(const float* __restrict__ left,  const float* __restrict__ right,
                const float* __restrict__ Wl,    const float* __restrict__ bl,
                const float* __restrict__ Wr,    const float* __restrict__ br,
                const float* __restrict__ Wconv, float* __restrict__ out)
{
    extern __shared__ float sm[];
    const int tid = threadIdx.x;
    const int b   = blockIdx.y;
    const int dg0 = blockIdx.x * TILE_D;   // global d of local col 1 (col 0 is d-1 halo)

    // ---------------- phase 0: stage Wl/Wr + raw tiles, zero B padding ----------------
    for (int i = tid; i < 4096; i += 256) {
        sm[OFF_WL + i] = Wl[i];
        sm[OFF_WR + i] = Wr[i];
    }
    const float* Lb = left  + (size_t)b * (Lc * Dc);
    const float* Rb = right + (size_t)b * (Lc * Dc);
    for (int i = tid; i < 64 * NS; i += 256) {
        int r = i / NS, c = i % NS;
        int d = dg0 + c - 1;
        float lv = 0.f, rv = 0.f;
        if ((unsigned)d < (unsigned)Dc) {
            lv = Lb[r * Dc + d];
            rv = Rb[r * Dc + d];
        }
        sm[OFF_A + r * SA + c]          = lv;
        sm[OFF_B + (64 + r) * SA + c]   = rv;   // B' lives in rows 64..127 (m = row-64)
        sm[OFF_B + r * SA + c]          = 0.f;  // pad rows 0..63
        sm[OFF_B + (128 + r) * SA + c]  = 0.f;  // pad rows 128..191
    }
    __syncthreads();

    // ---------------- phase 1: in-place linears (read-all -> sync -> write) ----------------
    for (int mat = 0; mat < 2; ++mat) {
        float raw[64];
        const bool active = tid < 132;          // 66 cols x 2 k-halves
        int col = 0, k0 = 0, base = 0;
        if (active) {
            col  = tid % 66;
            k0   = (tid / 66) * 32;
            base = mat ? (OFF_B + 64 * SA) : OFF_A;
            #pragma unroll
            for (int j = 0; j < 64; ++j) raw[j] = sm[base + j * SA + col];
        }
        __syncthreads();
        if (active) {
            const float* wb   = sm + (mat ? OFF_WR : OFF_WL);
            const float* bias = mat ? br : bl;
            for (int kk = 0; kk < 32; ++kk) {
                int k = k0 + kk;
                const float4* w4 = reinterpret_cast<const float4*>(wb + k * 64);
                float s0 = 0.f, s1 = 0.f, s2 = 0.f, s3 = 0.f;
                #pragma unroll
                for (int l4 = 0; l4 < 16; ++l4) {
                    float4 w = w4[l4];
                    s0 += w.x * raw[4 * l4 + 0];
                    s1 += w.y * raw[4 * l4 + 1];
                    s2 += w.z * raw[4 * l4 + 2];
                    s3 += w.w * raw[4 * l4 + 3];
                }
                sm[base + k * SA + col] = bias[k] + ((s0 + s1) + (s2 + s3));
            }
        }
        __syncthreads();
    }

    // ---------------- phase 2: dense correlation, 4-shift rolling window ----------------
    // corr[i,col] = sum_j a[j] * Bpad[(j+127-i), col]  (pad rows are zero)
    for (int round = 0; round < 2; ++round) {
        int item = tid + round * 256;
        if (item < 264) {                        // 66 cols x 4 i-blocks of 32
            int col = item % 66;
            int ib  = item / 66;
            int gd  = dg0 + col - 1;
            bool valid = (unsigned)gd < (unsigned)Dc;
            float a[64];
            #pragma unroll
            for (int j = 0; j < 64; ++j) a[j] = sm[OFF_A + j * SA + col];
            const float* bp = sm + OFF_B + col;
            for (int iq = 0; iq < 8; ++iq) {
                int i0 = ib * 32 + iq * 4;       // quad i0..i0+3
                float acc0 = 0.f, acc1 = 0.f, acc2 = 0.f, acc3 = 0.f;
                float b1 = bp[(126 - i0) * SA];
                float b2 = bp[(125 - i0) * SA];
                float b3 = bp[(124 - i0) * SA];
                #pragma unroll
                for (int j = 0; j < 64; ++j) {
                    float b0 = bp[(j + 127 - i0) * SA];
                    acc0 += a[j] * b0;
                    acc1 += a[j] * b1;
                    acc2 += a[j] * b2;
                    acc3 += a[j] * b3;
                    b3 = b2; b2 = b1; b1 = b0;
                }
                if (!valid) { acc0 = acc1 = acc2 = acc3 = 0.f; }  // halo at D edges = conv zero-pad
                sm[OFF_C + (i0 + 0) * SC + col] = acc0;
                sm[OFF_C + (i0 + 1) * SC + col] = acc1;
                sm[OFF_C + (i0 + 2) * SC + col] = acc2;
                sm[OFF_C + (i0 + 3) * SC + col] = acc3;
            }
        }
    }

    // ---------------- phase 3: conv(128->64, k=3) as register-tiled 4k x 4d ----------------
    const int dq = tid & 15, kq = tid >> 4;
    const int dd0 = dq * 4, k0 = kq * 4;
    float acc[4][4];
    #pragma unroll
    for (int i = 0; i < 4; ++i)
        #pragma unroll
        for (int j = 0; j < 4; ++j) acc[i][j] = 0.f;

    for (int half = 0; half < 2; ++half) {
        __syncthreads();   // corr writers / previous-half weight readers done
        for (int i = tid; i < 64 * 192; i += 256) {       // stage Wconv c-half (aliases OFF_B)
            int k = i / 192, r = i % 192;                 // r = cl*3 + t
            sm[OFF_B + k * WCS + r] = Wconv[k * 384 + half * 192 + r];
        }
        __syncthreads();
        for (int cl = 0; cl < 64; ++cl) {
            int c = half * 64 + cl;
            const float* crow = sm + OFF_C + c * SC + dd0;
            float4 c4 = *reinterpret_cast<const float4*>(crow);
            float cv[6] = { c4.x, c4.y, c4.z, c4.w, crow[4], crow[5] };
            const float* wrow = sm + OFF_B + k0 * WCS + cl * 3;
            #pragma unroll
            for (int kk = 0; kk < 4; ++kk) {
                float w0 = wrow[kk * WCS + 0];
                float w1 = wrow[kk * WCS + 1];
                float w2 = wrow[kk * WCS + 2];
                #pragma unroll
                for (int dd = 0; dd < 4; ++dd)
                    acc[kk][dd] += w0 * cv[dd] + w1 * cv[dd + 1] + w2 * cv[dd + 2];
            }
        }
    }

    float* ob = out + (size_t)b * (Lc * Dc) + dg0 + dd0;
    #pragma unroll
    for (int kk = 0; kk < 4; ++kk) {
        float4 v = make_float4(acc[kk][0], acc[kk][1], acc[kk][2], acc[kk][3]);
        *reinterpret_cast<float4*>(ob + (size_t)(k0 + kk) * Dc) = v;
    }
}

extern "C" void kernel_launch(void* const* d_in, const int* in_sizes, int n_in,
                              void* d_out, int out_size)
{
    (void)in_sizes; (void)n_in; (void)out_size;
    const float* left  = (const float*)d_in[0];
    const float* right = (const float*)d_in[1];
    const float* Wl    = (const float*)d_in[2];
    const float* bl    = (const float*)d_in[3];
    const float* Wr    = (const float*)d_in[4];
    const float* br    = (const float*)d_in[5];
    const float* Wconv = (const float*)d_in[6];
    float* out = (float*)d_out;

    cudaFuncSetAttribute(cc_fused_kernel,
                         cudaFuncAttributeMaxDynamicSharedMemorySize, SMEM_BYTES);
    dim3 grid(Dc / TILE_D, 256, 1);   // (16, 256) = 4096 CTAs, one batch x 64-col D-tile each
    cc_fused_kernel<<<grid, 256, SMEM_BYTES>>>(left, right, Wl, bl, Wr, br, Wconv, out);
}

// round 3
// speedup vs baseline: 1.8040x; 1.8040x over previous
#include <cuda_runtime.h>
#include <cstddef>

// Shapes: B=256, L=64, D=1024
// left'[b,k,d] = sum_l Wl[k,l]*left[b,l,d] + bl[k]            (same for right)
// corr[b,i,d]  = sum_j left'[b,j,d]*right'[b, j+63-i, d]      (i in [0,128), row 127 = 0)
// y[b,k,d]     = sum_c sum_t Wconv[k,c,t]*corr[b,c,d+t-1]     (zero-padded in d)

namespace {
constexpr int Lc = 64;
constexpr int Dc = 1024;
constexpr int TILE_D = 64;
constexpr int NS = 66;          // tile cols incl. 1-col halo each side
constexpr int SA = 66;          // stride for A / Bpad tiles
constexpr int SC = 68;          // stride for corr rows (16B aligned) & W^T rows
constexpr int OFF_A  = 0;                          // 64*66   left  raw -> left'
constexpr int OFF_B  = OFF_A + 64 * SA;            // 192*66  zero-padded right raw -> right'
constexpr int OFF_C  = OFF_B + 192 * SA;           // 128*68  corr; ALIASED: Wl^T,Wr^T (phase 1)
constexpr int OFF_WT = OFF_C;                      // Wl^T [l][k] stride 68 (4352 fl), Wr^T next
constexpr int WT_SZ  = 64 * SC;                    // 4352
constexpr int SMEM_FLOATS = OFF_C + 128 * SC;      // 25600 floats = 102400 B -> 2 CTAs/SM
constexpr int SMEM_BYTES  = SMEM_FLOATS * 4;
constexpr int WCS = 193;        // Wconv per-k stride (aliased at OFF_B; 64*193 <= 192*66)
}

__global__ void __launch_bounds__(256, 2)
cc_fused_kernel(const float* __restrict__ left,  const float* __restrict__ right,
                const float* __restrict__ Wl,    const float* __restrict__ bl,
                const float* __restrict__ Wr,    const float* __restrict__ br,
                const float* __restrict__ Wconv, float* __restrict__ out)
{
    extern __shared__ float sm[];
    const int tid = threadIdx.x;
    const int b   = blockIdx.y;
    const int dg0 = blockIdx.x * TILE_D;   // global d of local col 1 (col 0 is d-1 halo)

    // ---------------- phase 0: stage raw tiles (+zero pad) and W^T ----------------
    const float* Lb = left  + (size_t)b * (Lc * Dc);
    const float* Rb = right + (size_t)b * (Lc * Dc);
    for (int i = tid; i < 64 * NS; i += 256) {
        int r = i / NS, c = i % NS;
        int d = dg0 + c - 1;
        float lv = 0.f, rv = 0.f;
        if ((unsigned)d < (unsigned)Dc) {
            lv = Lb[r * Dc + d];
            rv = Rb[r * Dc + d];
        }
        sm[OFF_A + r * SA + c]          = lv;
        sm[OFF_B + (64 + r) * SA + c]   = rv;   // B' rows 64..127
        sm[OFF_B + r * SA + c]          = 0.f;  // pad rows 0..63
        sm[OFF_B + (128 + r) * SA + c]  = 0.f;  // pad rows 128..191
    }
    for (int i = tid; i < 8192; i += 256) {     // W^T staging into corr-alias region
        int which = i >> 12;                    // 0: Wl, 1: Wr
        int r = i & 4095;
        int k = r >> 6, l = r & 63;
        float w = which ? Wr[r] : Wl[r];
        sm[OFF_WT + which * WT_SZ + l * SC + k] = w;
    }
    __syncthreads();

    // ---------------- phase 1: linears (all 256 threads, balanced) ----------------
    {
        const int colI = 1 + (tid & 63);        // interior col
        const int grp  = tid >> 6;              // 0..3
        const int mat  = grp >> 1;              // 0: left(A), 1: right(B')
        const int k0   = (grp & 1) * 32;
        const int base = mat ? (OFF_B + 64 * SA) : OFF_A;

        float raw[64];
        #pragma unroll
        for (int l = 0; l < 64; ++l) raw[l] = sm[base + l * SA + colI];
        __syncthreads();                        // all raw cached before in-place writes

        const float4* wt4 = reinterpret_cast<const float4*>(sm + OFF_WT + mat * WT_SZ);
        const float* bias = mat ? br : bl;
        for (int kq = 0; kq < 8; ++kq) {
            int k = k0 + kq * 4;
            float a0 = 0.f, a1 = 0.f, a2 = 0.f, a3 = 0.f;
            #pragma unroll
            for (int l = 0; l < 64; ++l) {
                float4 w = wt4[l * (SC / 4) + (k >> 2)];   // broadcast LDS.128
                a0 += w.x * raw[l];
                a1 += w.y * raw[l];
                a2 += w.z * raw[l];
                a3 += w.w * raw[l];
            }
            sm[base + (k + 0) * SA + colI] = a0 + __ldg(bias + k + 0);
            sm[base + (k + 1) * SA + colI] = a1 + __ldg(bias + k + 1);
            sm[base + (k + 2) * SA + colI] = a2 + __ldg(bias + k + 2);
            sm[base + (k + 3) * SA + colI] = a3 + __ldg(bias + k + 3);
        }

        // halo cols (0, 65): 2 mats x 2 cols x 64 k = 256 one-output items
        const int hmat = tid >> 7;
        const int hcol = (tid & 64) ? 65 : 0;
        const int hk   = tid & 63;
        const int hbase = hmat ? (OFF_B + 64 * SA) : OFF_A;
        float rawh[64];
        #pragma unroll
        for (int l = 0; l < 64; ++l) rawh[l] = sm[hbase + l * SA + hcol];
        __syncthreads();                        // halo raw cached before halo writes
        const float* wt = sm + OFF_WT + hmat * WT_SZ;
        float acc = 0.f;
        #pragma unroll
        for (int l = 0; l < 64; ++l) acc += wt[l * SC + hk] * rawh[l];
        sm[hbase + hk * SA + hcol] = acc + __ldg((hmat ? br : bl) + hk);
    }
    __syncthreads();

    // ---------------- phase 2: correlation (balanced: 64 cols x 4 i-groups) ----------------
    {
        const int col = 1 + (tid & 63);
        const int ig  = tid >> 6;               // 0..3 -> i in [ig*32, ig*32+32)
        float a[64];
        #pragma unroll
        for (int j = 0; j < 64; ++j) a[j] = sm[OFF_A + j * SA + col];
        const float* bp = sm + OFF_B + col;
        for (int iq = 0; iq < 8; ++iq) {
            int i0 = ig * 32 + iq * 4;
            float acc0 = 0.f, acc1 = 0.f, acc2 = 0.f, acc3 = 0.f;
            float b1 = bp[(126 - i0) * SA];
            float b2 = bp[(125 - i0) * SA];
            float b3 = bp[(124 - i0) * SA];
            #pragma unroll
            for (int j = 0; j < 64; ++j) {
                float b0 = bp[(j + 127 - i0) * SA];
                acc0 += a[j] * b0;
                acc1 += a[j] * b1;
                acc2 += a[j] * b2;
                acc3 += a[j] * b3;
                b3 = b2; b2 = b1; b1 = b0;
            }
            sm[OFF_C + (i0 + 0) * SC + col] = acc0;
            sm[OFF_C + (i0 + 1) * SC + col] = acc1;
            sm[OFF_C + (i0 + 2) * SC + col] = acc2;
            sm[OFF_C + (i0 + 3) * SC + col] = acc3;
        }

        // halo cols: 2 cols x 128 i = 256 one-output items
        const int hcol = (tid >> 7) ? 65 : 0;
        const int hi   = tid & 127;
        const int gd   = dg0 + hcol - 1;
        const bool valid = (unsigned)gd < (unsigned)Dc;
        const float* ap  = sm + OFF_A + hcol;
        const float* bph = sm + OFF_B + hcol;
        float acc = 0.f;
        #pragma unroll
        for (int j = 0; j < 64; ++j)
            acc += ap[j * SA] * bph[(j + 127 - hi) * SA];
        sm[OFF_C + hi * SC + hcol] = valid ? acc : 0.f;   // D-edge = conv zero-pad
    }

    // ---------------- phase 3: conv(128->64, k=3), register-tiled 4k x 4d ----------------
    const int dq = tid & 15, kq = tid >> 4;
    const int dd0 = dq * 4, k0c = kq * 4;
    float acc[4][4];
    #pragma unroll
    for (int i = 0; i < 4; ++i)
        #pragma unroll
        for (int j = 0; j < 4; ++j) acc[i][j] = 0.f;

    for (int half = 0; half < 2; ++half) {
        __syncthreads();   // corr/B readers done before (re)staging Wconv over B
        for (int i = tid; i < 64 * 192; i += 256) {       // stage Wconv c-half (aliases OFF_B)
            int k = i / 192, r = i % 192;                 // r = cl*3 + t
            sm[OFF_B + k * WCS + r] = Wconv[k * 384 + half * 192 + r];
        }
        __syncthreads();
        for (int cl = 0; cl < 64; ++cl) {
            int c = half * 64 + cl;
            const float* crow = sm + OFF_C + c * SC + dd0;
            float4 c4 = *reinterpret_cast<const float4*>(crow);
            float cv[6] = { c4.x, c4.y, c4.z, c4.w, crow[4], crow[5] };
            const float* wrow = sm + OFF_B + k0c * WCS + cl * 3;
            #pragma unroll
            for (int kk = 0; kk < 4; ++kk) {
                float w0 = wrow[kk * WCS + 0];
                float w1 = wrow[kk * WCS + 1];
                float w2 = wrow[kk * WCS + 2];
                #pragma unroll
                for (int dd = 0; dd < 4; ++dd)
                    acc[kk][dd] += w0 * cv[dd] + w1 * cv[dd + 1] + w2 * cv[dd + 2];
            }
        }
    }

    float* ob = out + (size_t)b * (Lc * Dc) + dg0 + dd0;
    #pragma unroll
    for (int kk = 0; kk < 4; ++kk) {
        float4 v = make_float4(acc[kk][0], acc[kk][1], acc[kk][2], acc[kk][3]);
        *reinterpret_cast<float4*>(ob + (size_t)(k0c + kk) * Dc) = v;
    }
}

extern "C" void kernel_launch(void* const* d_in, const int* in_sizes, int n_in,
                              void* d_out, int out_size)
{
    (void)in_sizes; (void)n_in; (void)out_size;
    const float* left  = (const float*)d_in[0];
    const float* right = (const float*)d_in[1];
    const float* Wl    = (const float*)d_in[2];
    const float* bl    = (const float*)d_in[3];
    const float* Wr    = (const float*)d_in[4];
    const float* br    = (const float*)d_in[5];
    const float* Wconv = (const float*)d_in[6];
    float* out = (float*)d_out;

    cudaFuncSetAttribute(cc_fused_kernel,
                         cudaFuncAttributeMaxDynamicSharedMemorySize, SMEM_BYTES);
    dim3 grid(Dc / TILE_D, 256, 1);   // 4096 CTAs, one batch x 64-col D-tile each
    cc_fused_kernel<<<grid, 256, SMEM_BYTES>>>(left, right, Wl, bl, Wr, br, Wconv, out);
}

// round 4
// speedup vs baseline: 2.0981x; 1.1630x over previous
#include <cuda_runtime.h>
#include <cstddef>

typedef unsigned long long u64;

__device__ __forceinline__ u64 pk2(float lo, float hi) {
    u64 r; asm("mov.b64 %0,{%1,%2};" : "=l"(r) : "f"(lo), "f"(hi)); return r;
}
__device__ __forceinline__ void upk2(u64 v, float& lo, float& hi) {
    asm("mov.b64 {%0,%1},%2;" : "=f"(lo), "=f"(hi) : "l"(v));
}
__device__ __forceinline__ void fma2(u64& d, u64 a, u64 b) {
    asm("fma.rn.f32x2 %0,%1,%2,%0;" : "+l"(d) : "l"(a), "l"(b));
}

// Shapes: B=256, L=64, D=1024
// left'[b,k,d] = sum_l Wl[k,l]*left[b,l,d] + bl[k]            (same for right)
// corr[b,i,d]  = sum_j left'[b,j,d]*right'[b, j+63-i, d]      (i in [0,128), row 127 = 0)
// y[b,k,d]     = sum_c sum_t Wconv[k,c,t]*corr[b,c,d+t-1]     (zero-padded in d)

namespace {
constexpr int Lc = 64;
constexpr int Dc = 1024;
constexpr int TILE_D = 64;
constexpr int ST = 68;          // row stride (floats) for A, Bpad, corr, W^T
// A/B rows: tile col c (0..65, incl halo) stored at float offset c+1 -> interior
// cols 1..64 sit at even offsets 2..65 (8B-aligned for LDS.64 pairs).
// corr rows: col c stored at offset c (so phase-3 cv blocks at d0 are 16B-aligned).
constexpr int OFF_A  = 0;                          // 64 rows   left raw -> left'
constexpr int OFF_B  = OFF_A + 64 * ST;            // 192 rows  zero-padded right raw -> right'
constexpr int OFF_C  = OFF_B + 192 * ST;           // 128 rows  corr; ALIASED: Wl^T,Wr^T ph1; Wconv-pairs alias OFF_B in ph3
constexpr int OFF_WT = OFF_C;
constexpr int WT_SZ  = 64 * ST;                    // 4352 floats per mat; 2 mats = 8704 = corr region
constexpr int SMEM_FLOATS = OFF_C + 128 * ST;      // 26112 floats = 104448 B -> 2 CTAs/SM
constexpr int SMEM_BYTES  = SMEM_FLOATS * 4;
}

__global__ void __launch_bounds__(256, 2)
cc_fused_kernel(const float* __restrict__ left,  const float* __restrict__ right,
                const float* __restrict__ Wl,    const float* __restrict__ bl,
                const float* __restrict__ Wr,    const float* __restrict__ br,
                const float* __restrict__ Wconv, float* __restrict__ out)
{
    extern __shared__ float sm[];
    const int tid = threadIdx.x;
    const int b   = blockIdx.y;
    const int dg0 = blockIdx.x * TILE_D;   // global d of tile col 1 (col 0 is d-1 halo)

    // ---------------- phase 0: stage raw tiles (+zero pad) and W^T ----------------
    const float* Lb = left  + (size_t)b * (Lc * Dc);
    const float* Rb = right + (size_t)b * (Lc * Dc);
    for (int i = tid; i < 64 * 66; i += 256) {
        int r = i / 66, c = i % 66;
        int d = dg0 + c - 1;
        float lv = 0.f, rv = 0.f;
        if ((unsigned)d < (unsigned)Dc) {
            lv = Lb[r * Dc + d];
            rv = Rb[r * Dc + d];
        }
        sm[OFF_A + r * ST + c + 1]          = lv;
        sm[OFF_B + (64 + r) * ST + c + 1]   = rv;   // B' rows 64..127
        sm[OFF_B + r * ST + c + 1]          = 0.f;  // pad rows 0..63
        sm[OFF_B + (128 + r) * ST + c + 1]  = 0.f;  // pad rows 128..191
    }
    for (int i = tid; i < 8192; i += 256) {     // W^T staging into corr-alias region
        int which = i >> 12;                    // 0: Wl, 1: Wr
        int r = i & 4095;
        int k = r >> 6, l = r & 63;
        float w = which ? Wr[r] : Wl[r];
        sm[OFF_WT + which * WT_SZ + l * ST + k] = w;
    }
    __syncthreads();

    // ---------------- phase 1: linears (scalar, broadcast LDS.128 weights) ----------------
    {
        const int oI   = (tid & 63) + 2;        // interior col smem offset (col 1..64 -> 2..65)
        const int grp  = tid >> 6;
        const int mat  = grp >> 1;              // 0: left(A), 1: right(B')
        const int k0   = (grp & 1) * 32;
        const int base = mat ? (OFF_B + 64 * ST) : OFF_A;

        float raw[64];
        #pragma unroll
        for (int l = 0; l < 64; ++l) raw[l] = sm[base + l * ST + oI];
        __syncthreads();                        // all raw cached before in-place writes

        const float4* wt4 = reinterpret_cast<const float4*>(sm + OFF_WT + mat * WT_SZ);
        const float* bias = mat ? br : bl;
        for (int kq = 0; kq < 8; ++kq) {
            int k = k0 + kq * 4;
            float a0 = 0.f, a1 = 0.f, a2 = 0.f, a3 = 0.f;
            #pragma unroll
            for (int l = 0; l < 64; ++l) {
                float4 w = wt4[l * (ST / 4) + (k >> 2)];   // broadcast LDS.128
                a0 += w.x * raw[l];
                a1 += w.y * raw[l];
                a2 += w.z * raw[l];
                a3 += w.w * raw[l];
            }
            sm[base + (k + 0) * ST + oI] = a0 + __ldg(bias + k + 0);
            sm[base + (k + 1) * ST + oI] = a1 + __ldg(bias + k + 1);
            sm[base + (k + 2) * ST + oI] = a2 + __ldg(bias + k + 2);
            sm[base + (k + 3) * ST + oI] = a3 + __ldg(bias + k + 3);
        }

        // halo cols (tile col 0 -> off 1, col 65 -> off 66): 2 mats x 2 cols x 64 k
        const int hmat = tid >> 7;
        const int hoff = (tid & 64) ? 66 : 1;
        const int hk   = tid & 63;
        const int hbase = hmat ? (OFF_B + 64 * ST) : OFF_A;
        float rawh[64];
        #pragma unroll
        for (int l = 0; l < 64; ++l) rawh[l] = sm[hbase + l * ST + hoff];
        __syncthreads();                        // halo raw cached before halo writes
        const float* wt = sm + OFF_WT + hmat * WT_SZ;
        float acc = 0.f;
        #pragma unroll
        for (int l = 0; l < 64; ++l) acc += wt[l * ST + hk] * rawh[l];
        sm[hbase + hk * ST + hoff] = acc + __ldg((hmat ? br : bl) + hk);
    }
    __syncthreads();

    // ---------------- phase 2: correlation, d-packed f32x2, 8-wide i-window ----------------
    {
        const int cp = tid & 31;                // column pair: tile cols (1+2cp, 2+2cp)
        const int ig = tid >> 5;                // 8 i-groups of 16
        const u64* ap = reinterpret_cast<const u64*>(sm + OFF_A) + (cp + 1);   // float off 2cp+2
        const u64* bp = reinterpret_cast<const u64*>(sm + OFF_B) + (cp + 1);
        // row stride in u64 = ST/2 = 34
        #pragma unroll 1
        for (int oct = 0; oct < 2; ++oct) {
            const int i0 = ig * 16 + oct * 8;
            u64 acc[8], win[8];
            #pragma unroll
            for (int q = 0; q < 8; ++q) acc[q] = 0ull;
            #pragma unroll
            for (int q = 1; q < 8; ++q) win[q] = bp[(127 - i0 - q) * 34];
            #pragma unroll 1
            for (int jh = 0; jh < 4; ++jh) {
                u64 a2[16];
                #pragma unroll
                for (int t = 0; t < 16; ++t) a2[t] = ap[(jh * 16 + t) * 34];
                #pragma unroll
                for (int t = 0; t < 16; ++t) {
                    const int j = jh * 16 + t;
                    u64 nv = bp[(j + 127 - i0) * 34];
                    fma2(acc[0], a2[t], nv);
                    #pragma unroll
                    for (int q = 1; q < 8; ++q) fma2(acc[q], a2[t], win[q]);
                    #pragma unroll
                    for (int q = 7; q > 1; --q) win[q] = win[q - 1];
                    win[1] = nv;
                }
            }
            #pragma unroll
            for (int q = 0; q < 8; ++q) {
                float lo, hi; upk2(acc[q], lo, hi);
                sm[OFF_C + (i0 + q) * ST + 1 + 2 * cp] = lo;   // corr col c at offset c
                sm[OFF_C + (i0 + q) * ST + 2 + 2 * cp] = hi;
            }
        }

        // halo: 2 cols x 128 i, scalar
        const int hcol = (tid >> 7) ? 65 : 0;
        const int hoff = hcol ? 66 : 1;
        const int hi   = tid & 127;
        const int gd   = dg0 + hcol - 1;
        const bool valid = (unsigned)gd < (unsigned)Dc;
        float acc = 0.f;
        #pragma unroll
        for (int j = 0; j < 64; ++j)
            acc += sm[OFF_A + j * ST + hoff] * sm[OFF_B + (j + 127 - hi) * ST + hoff];
        sm[OFF_C + hi * ST + hcol] = valid ? acc : 0.f;   // D-edge = conv zero-pad
    }

    // ---------------- phase 3: conv(128->64,k=3), k-packed f32x2, prepacked weights ----------------
    const int dq = tid & 15, kq = tid >> 4;
    const int d0 = dq * 4;
    u64 acc3[2][4];
    #pragma unroll
    for (int p = 0; p < 2; ++p)
        #pragma unroll
        for (int dd = 0; dd < 4; ++dd) acc3[p][dd] = 0ull;

    u64* wp = reinterpret_cast<u64*>(sm + OFF_B);   // pairs: wp[kp*192 + cl*3 + t] = {W[2kp], W[2kp+1]}
    #pragma unroll 1
    for (int half = 0; half < 2; ++half) {
        __syncthreads();   // corr/B readers done before staging Wconv pairs over B
        for (int i = tid; i < 32 * 192; i += 256) {
            int kp = i / 192, r = i % 192;          // r = cl*3 + t
            const float* wsrc = Wconv + half * 192 + r;
            wp[kp * 192 + r] = pk2(__ldg(wsrc + (2 * kp) * 384),
                                   __ldg(wsrc + (2 * kp + 1) * 384));
        }
        __syncthreads();
        const u64* wb = wp + (2 * kq) * 192;
        #pragma unroll 4
        for (int cl = 0; cl < 64; ++cl) {
            const float* crow = sm + OFF_C + (half * 64 + cl) * ST + d0;
            float4 c4 = *reinterpret_cast<const float4*>(crow);
            float2 ct = *reinterpret_cast<const float2*>(crow + 4);
            u64 cv[6] = { pk2(c4.x, c4.x), pk2(c4.y, c4.y), pk2(c4.z, c4.z),
                          pk2(c4.w, c4.w), pk2(ct.x, ct.x), pk2(ct.y, ct.y) };
            #pragma unroll
            for (int p = 0; p < 2; ++p) {
                const u64* wr = wb + p * 192 + cl * 3;
                u64 w0 = wr[0], w1 = wr[1], w2 = wr[2];
                #pragma unroll
                for (int dd = 0; dd < 4; ++dd) {
                    fma2(acc3[p][dd], w0, cv[dd]);
                    fma2(acc3[p][dd], w1, cv[dd + 1]);
                    fma2(acc3[p][dd], w2, cv[dd + 2]);
                }
            }
        }
    }

    // stores: lane writes rows (4kq+2p, 4kq+2p+1), 4 consecutive d each; L2 write-combines
    float* ob = out + (size_t)b * (Lc * Dc) + dg0 + d0;
    #pragma unroll
    for (int p = 0; p < 2; ++p) {
        const int k0 = 4 * kq + 2 * p;
        #pragma unroll
        for (int dd = 0; dd < 4; ++dd) {
            float lo, hi; upk2(acc3[p][dd], lo, hi);
            ob[(size_t)k0 * Dc + dd]       = lo;
            ob[(size_t)(k0 + 1) * Dc + dd] = hi;
        }
    }
}

extern "C" void kernel_launch(void* const* d_in, const int* in_sizes, int n_in,
                              void* d_out, int out_size)
{
    (void)in_sizes; (void)n_in; (void)out_size;
    const float* left  = (const float*)d_in[0];
    const float* right = (const float*)d_in[1];
    const float* Wl    = (const float*)d_in[2];
    const float* bl    = (const float*)d_in[3];
    const float* Wr    = (const float*)d_in[4];
    const float* br    = (const float*)d_in[5];
    const float* Wconv = (const float*)d_in[6];
    float* out = (float*)d_out;

    cudaFuncSetAttribute(cc_fused_kernel,
                         cudaFuncAttributeMaxDynamicSharedMemorySize, SMEM_BYTES);
    dim3 grid(Dc / TILE_D, 256, 1);   // 4096 CTAs, one batch x 64-col D-tile each
    cc_fused_kernel<<<grid, 256, SMEM_BYTES>>>(left, right, Wl, bl, Wr, br, Wconv, out);
}